// round 14
// baseline (speedup 1.0000x reference)
#include <cuda_runtime.h>

// Problem constants
#define BATCH 32
#define SEQ   512
#define DIM   64
#define VOCAB 32000
#define DECAY 0.9f

#define T_CHUNK 16
#define NCHUNK  32                      // SEQ / T_CHUNK
#define DC      0.1853020188851841f     // 0.9^16 (chunk decay)
#define MTERMS  6                       // carry terms kept; err ~0.9^96 = 4.1e-5

// Scratch: per-chunk local sums L_k [B][NCHUNK][D][D] = 16 MB (L2-resident)
__device__ float g_L[BATCH * NCHUNK * DIM * DIM];

// W[s] = 0.9^((15-s)/2): pre-scale so L accumulates with pure FFMA.
__device__ __constant__ float c_W[T_CHUNK] = {
    0.45375228053933687f, 0.47829690000000000f, 0.50416920059926320f,
    0.53144100000000000f, 0.56018800066584800f, 0.59049000000000000f,
    0.62243111185094220f, 0.65610000000000000f, 0.69159012427882460f,
    0.72900000000000000f, 0.76843347142091620f, 0.81000000000000000f,
    0.85381496824546250f, 0.90000000000000000f, 0.94868329805051380f,
    1.00000000000000000f
};

// ---------------------------------------------------------------------------
// Kernel B1: gather (pre-scaled) + local decayed sums, TWO chunks per block.
// Both chunks' LDG chains issued up-front (MLP=2) to halve latency exposure;
// two independent accumulator sets double FFMA ILP. Grid = 512 blocks.
// ---------------------------------------------------------------------------
__global__ __launch_bounds__(256)
void qmn_chunk_sum(const int* __restrict__ x, const float* __restrict__ emb) {
    __shared__ __align__(16) float sc[2][T_CHUNK * DIM];   // 2 x 4 KB

    const int b   = blockIdx.x >> 4;   // 16 chunk-pairs per batch
    const int g   = blockIdx.x & 15;   // chunk pair -> chunks 2g, 2g+1
    const int tid = threadIdx.x;

    {   // Issue both chunks' gathers before any wait (independent chains)
        const int s  = tid >> 4;
        const int d4 = tid & 15;
        const int tokbase = b * SEQ + g * 2 * T_CHUNK + s;
        int tok0 = x[tokbase];
        int tok1 = x[tokbase + T_CHUNK];
        tok0 = min(max(tok0, 0), VOCAB - 1);
        tok1 = min(max(tok1, 0), VOCAB - 1);
        float4 v0 = reinterpret_cast<const float4*>(emb + (size_t)tok0 * DIM)[d4];
        float4 v1 = reinterpret_cast<const float4*>(emb + (size_t)tok1 * DIM)[d4];
        const float w = c_W[s];
        v0.x *= w; v0.y *= w; v0.z *= w; v0.w *= w;
        v1.x *= w; v1.y *= w; v1.z *= w; v1.w *= w;
        reinterpret_cast<float4*>(sc[0])[tid] = v0;
        reinterpret_cast<float4*>(sc[1])[tid] = v1;
    }
    __syncthreads();

    const int i0 = (tid >> 4) * 4;
    const int j0 = (tid & 15) * 4;

    float4 L0[4], L1[4];
    #pragma unroll
    for (int r = 0; r < 4; r++) {
        L0[r] = make_float4(0.f, 0.f, 0.f, 0.f);
        L1[r] = make_float4(0.f, 0.f, 0.f, 0.f);
    }

    #pragma unroll
    for (int t = 0; t < T_CHUNK; t++) {
        const float4 ci0 = *reinterpret_cast<const float4*>(sc[0] + t * DIM + i0);
        const float4 cj0 = *reinterpret_cast<const float4*>(sc[0] + t * DIM + j0);
        const float4 ci1 = *reinterpret_cast<const float4*>(sc[1] + t * DIM + i0);
        const float4 cj1 = *reinterpret_cast<const float4*>(sc[1] + t * DIM + j0);
        const float c0[4] = {ci0.x, ci0.y, ci0.z, ci0.w};
        const float c1[4] = {ci1.x, ci1.y, ci1.z, ci1.w};
        #pragma unroll
        for (int r = 0; r < 4; r++) {
            L0[r].x = fmaf(c0[r], cj0.x, L0[r].x);
            L0[r].y = fmaf(c0[r], cj0.y, L0[r].y);
            L0[r].z = fmaf(c0[r], cj0.z, L0[r].z);
            L0[r].w = fmaf(c0[r], cj0.w, L0[r].w);
            L1[r].x = fmaf(c1[r], cj1.x, L1[r].x);
            L1[r].y = fmaf(c1[r], cj1.y, L1[r].y);
            L1[r].z = fmaf(c1[r], cj1.z, L1[r].z);
            L1[r].w = fmaf(c1[r], cj1.w, L1[r].w);
        }
    }

    float* Lp0 = g_L + ((size_t)b * NCHUNK + g * 2) * DIM * DIM;
    float* Lp1 = Lp0 + DIM * DIM;
    #pragma unroll
    for (int r = 0; r < 4; r++) {
        __stcg(reinterpret_cast<float4*>(Lp0 + (i0 + r) * DIM + j0), L0[r]);
        __stcg(reinterpret_cast<float4*>(Lp1 + (i0 + r) * DIM + j0), L1[r]);
    }
}

// ---------------------------------------------------------------------------
// Kernel C: state emission (1024 blocks), PDL-launched: gather prologue
// overlaps B1's tail; cudaGridDependencySynchronize() gates g_L reads.
// ---------------------------------------------------------------------------
__global__ __launch_bounds__(256)
void qmn_states(const int* __restrict__ x, const float* __restrict__ emb,
                float* __restrict__ out) {
    __shared__ __align__(16) float sc[T_CHUNK * DIM];   // 4 KB

    const int b   = blockIdx.x >> 5;
    const int k   = blockIdx.x & 31;
    const int tid = threadIdx.x;

    // ---- Gather this chunk's content — independent of B1, overlaps it ----
    {
        const int s  = tid >> 4;
        const int d4 = tid & 15;
        int tok = x[b * SEQ + k * T_CHUNK + s];
        tok = min(max(tok, 0), VOCAB - 1);
        reinterpret_cast<float4*>(sc)[tid] =
            reinterpret_cast<const float4*>(emb + (size_t)tok * DIM)[d4];
    }

    const int i0 = (tid >> 4) * 4;
    const int j0 = (tid & 15) * 4;

    // ---- Wait for B1's grid (and its g_L writes) before the carry reads ----
    cudaGridDependencySynchronize();

    // ---- Truncated carry: acc = sum_m DC^{k-1-m} L_m (+ DC^k I if k<=MTERMS)
    float4 acc[4];
    #pragma unroll
    for (int r = 0; r < 4; r++) acc[r] = make_float4(0.f, 0.f, 0.f, 0.f);

    const float* Lb = g_L + (size_t)b * NCHUNK * DIM * DIM;
    const int mlo = (k - MTERMS > 0) ? (k - MTERMS) : 0;
    float w = 1.0f;
    for (int m = k - 1; m >= mlo; m--) {
        const float* Lp = Lb + (size_t)m * DIM * DIM;
        #pragma unroll
        for (int r = 0; r < 4; r++) {
            const float4 l = *reinterpret_cast<const float4*>(Lp + (i0 + r) * DIM + j0);
            acc[r].x = fmaf(w, l.x, acc[r].x);
            acc[r].y = fmaf(w, l.y, acc[r].y);
            acc[r].z = fmaf(w, l.z, acc[r].z);
            acc[r].w = fmaf(w, l.w, acc[r].w);
        }
        w *= DC;
    }
    if (k <= MTERMS) {                 // loop ran k times -> w == DC^k
        #pragma unroll
        for (int r = 0; r < 4; r++) {
            const int i = i0 + r;
            if (i == j0 + 0) acc[r].x += w;
            if (i == j0 + 1) acc[r].y += w;
            if (i == j0 + 2) acc[r].z += w;
            if (i == j0 + 3) acc[r].w += w;
        }
    }

    __syncthreads();

    // ---- Emit 16 states, barrier-free, streaming stores ----
    float* op = out + ((size_t)b * SEQ + (size_t)k * T_CHUNK) * DIM * DIM;

    #pragma unroll
    for (int t = 0; t < T_CHUNK; t++) {
        const float4 ci = *reinterpret_cast<const float4*>(sc + t * DIM + i0);
        const float4 cj = *reinterpret_cast<const float4*>(sc + t * DIM + j0);
        const float c[4] = {ci.x, ci.y, ci.z, ci.w};
        #pragma unroll
        for (int r = 0; r < 4; r++) {
            acc[r].x = fmaf(acc[r].x, DECAY, c[r] * cj.x);
            acc[r].y = fmaf(acc[r].y, DECAY, c[r] * cj.y);
            acc[r].z = fmaf(acc[r].z, DECAY, c[r] * cj.z);
            acc[r].w = fmaf(acc[r].w, DECAY, c[r] * cj.w);
        }
        float* ot = op + (size_t)t * DIM * DIM;
        #pragma unroll
        for (int r = 0; r < 4; r++)
            __stcs(reinterpret_cast<float4*>(ot + (i0 + r) * DIM + j0), acc[r]);
    }
}

// ---------------------------------------------------------------------------
// Launch: B1 (512 blocks), then states with Programmatic Dependent Launch.
// ---------------------------------------------------------------------------
extern "C" void kernel_launch(void* const* d_in, const int* in_sizes, int n_in,
                              void* d_out, int out_size) {
    const int*   x   = (const int*)d_in[0];     // [B, S] int32
    const float* emb = (const float*)d_in[1];   // [VOCAB, D] fp32
    float*       out = (float*)d_out;           // [B, S, D, D] fp32

    (void)in_sizes; (void)n_in; (void)out_size;

    qmn_chunk_sum<<<BATCH * NCHUNK / 2, 256>>>(x, emb);

    cudaLaunchConfig_t cfg = {};
    cfg.gridDim  = dim3(BATCH * NCHUNK, 1, 1);
    cfg.blockDim = dim3(256, 1, 1);
    cfg.dynamicSmemBytes = 0;
    cudaLaunchAttribute attr[1];
    attr[0].id = cudaLaunchAttributeProgrammaticStreamSerialization;
    attr[0].val.programmaticStreamSerializationAllowed = 1;
    cfg.attrs = attr;
    cfg.numAttrs = 1;
    cudaLaunchKernelEx(&cfg, qmn_states, x, emb, out);
}

// round 15
// speedup vs baseline: 1.1463x; 1.1463x over previous
#include <cuda_runtime.h>

// Problem constants
#define BATCH 32
#define SEQ   512
#define DIM   64
#define VOCAB 32000
#define DECAY 0.9f

#define T_CHUNK 16
#define NCHUNK  32                      // SEQ / T_CHUNK
#define DC      0.1853020188851841f     // 0.9^16 (chunk decay)
#define MTERMS  8                       // carry terms kept; err ~0.9^128 = 1.4e-6

// Scratch: per-chunk local sums L_k [B][NCHUNK][D][D] = 16 MB (L2-resident)
__device__ float g_L[BATCH * NCHUNK * DIM * DIM];

// W[s] = 0.9^((15-s)/2): pre-scale so L accumulates with pure FFMA.
__device__ __constant__ float c_W[T_CHUNK] = {
    0.45375228053933687f, 0.47829690000000000f, 0.50416920059926320f,
    0.53144100000000000f, 0.56018800066584800f, 0.59049000000000000f,
    0.62243111185094220f, 0.65610000000000000f, 0.69159012427882460f,
    0.72900000000000000f, 0.76843347142091620f, 0.81000000000000000f,
    0.85381496824546250f, 0.90000000000000000f, 0.94868329805051380f,
    1.00000000000000000f
};

// 256-bit streaming store (sm_100+ / PTX ISA 8.8): one STG.256.
__device__ __forceinline__ void stg256_cs(float* p, const float v[8]) {
    asm volatile(
        "st.global.cs.v8.f32 [%0], {%1,%2,%3,%4,%5,%6,%7,%8};"
        :: "l"(p), "f"(v[0]), "f"(v[1]), "f"(v[2]), "f"(v[3]),
           "f"(v[4]), "f"(v[5]), "f"(v[6]), "f"(v[7])
        : "memory");
}

// ---------------------------------------------------------------------------
// Kernel B1: gather (pre-scaled) + per-chunk local decayed sums.
// R10 scalar form, 1024 blocks (proven best).
// ---------------------------------------------------------------------------
__global__ __launch_bounds__(256)
void qmn_chunk_sum(const int* __restrict__ x, const float* __restrict__ emb) {
    __shared__ __align__(16) float sc[T_CHUNK * DIM];   // 4 KB

    const int b   = blockIdx.x >> 5;   // NCHUNK = 32
    const int k   = blockIdx.x & 31;
    const int tid = threadIdx.x;

    {   // one float4 per thread, scaled by W[s]
        const int s  = tid >> 4;
        const int d4 = tid & 15;
        int tok = x[b * SEQ + k * T_CHUNK + s];
        tok = min(max(tok, 0), VOCAB - 1);
        float4 v = reinterpret_cast<const float4*>(emb + (size_t)tok * DIM)[d4];
        const float w = c_W[s];
        v.x *= w; v.y *= w; v.z *= w; v.w *= w;
        reinterpret_cast<float4*>(sc)[tid] = v;
    }
    __syncthreads();

    const int i0 = (tid >> 4) * 4;
    const int j0 = (tid & 15) * 4;

    float4 L[4];
    #pragma unroll
    for (int r = 0; r < 4; r++) L[r] = make_float4(0.f, 0.f, 0.f, 0.f);

    #pragma unroll
    for (int t = 0; t < T_CHUNK; t++) {
        const float4 ci = *reinterpret_cast<const float4*>(sc + t * DIM + i0);
        const float4 cj = *reinterpret_cast<const float4*>(sc + t * DIM + j0);
        const float c[4] = {ci.x, ci.y, ci.z, ci.w};
        #pragma unroll
        for (int r = 0; r < 4; r++) {
            L[r].x = fmaf(c[r], cj.x, L[r].x);
            L[r].y = fmaf(c[r], cj.y, L[r].y);
            L[r].z = fmaf(c[r], cj.z, L[r].z);
            L[r].w = fmaf(c[r], cj.w, L[r].w);
        }
    }

    float* Lp = g_L + (size_t)blockIdx.x * DIM * DIM;
    #pragma unroll
    for (int r = 0; r < 4; r++)
        __stcg(reinterpret_cast<float4*>(Lp + (i0 + r) * DIM + j0), L[r]);
}

// ---------------------------------------------------------------------------
// Kernel C: state emission, 2x8 thread tile + STG.256 stores.
//   thread tile: rows i0..i0+1 (i0 = (tid>>3)*2), cols j0..j0+7 (j0=(tid&7)*8)
// Per step: LDS.64 (ci) + 2 LDS.128 (cj) + 16 FFMA + 2 STG.256.
// PDL-launched; cudaGridDependencySynchronize() gates g_L reads.
// ---------------------------------------------------------------------------
__global__ __launch_bounds__(256)
void qmn_states(const int* __restrict__ x, const float* __restrict__ emb,
                float* __restrict__ out) {
    __shared__ __align__(16) float sc[T_CHUNK * DIM];   // 4 KB

    const int b   = blockIdx.x >> 5;
    const int k   = blockIdx.x & 31;
    const int tid = threadIdx.x;

    // ---- Gather this chunk's content — independent of B1, overlaps it ----
    {
        const int s  = tid >> 4;
        const int d4 = tid & 15;
        int tok = x[b * SEQ + k * T_CHUNK + s];
        tok = min(max(tok, 0), VOCAB - 1);
        reinterpret_cast<float4*>(sc)[tid] =
            reinterpret_cast<const float4*>(emb + (size_t)tok * DIM)[d4];
    }

    const int i0 = (tid >> 3) * 2;     // row pair
    const int j0 = (tid & 7) * 8;      // 8-col group

    // ---- Wait for B1's grid (and its g_L writes) before the carry reads ----
    cudaGridDependencySynchronize();

    // ---- Truncated carry: acc = sum_m DC^{k-1-m} L_m (+ DC^k I if k<=MTERMS)
    float acc[2][8];
    #pragma unroll
    for (int r = 0; r < 2; r++)
        #pragma unroll
        for (int c = 0; c < 8; c++) acc[r][c] = 0.0f;

    const float* Lb = g_L + (size_t)b * NCHUNK * DIM * DIM;
    const int mlo = (k - MTERMS > 0) ? (k - MTERMS) : 0;
    float w = 1.0f;
    for (int m = k - 1; m >= mlo; m--) {
        const float* Lp = Lb + (size_t)m * DIM * DIM;
        #pragma unroll
        for (int r = 0; r < 2; r++) {
            const float4 a = *reinterpret_cast<const float4*>(Lp + (i0 + r) * DIM + j0);
            const float4 d = *reinterpret_cast<const float4*>(Lp + (i0 + r) * DIM + j0 + 4);
            acc[r][0] = fmaf(w, a.x, acc[r][0]);
            acc[r][1] = fmaf(w, a.y, acc[r][1]);
            acc[r][2] = fmaf(w, a.z, acc[r][2]);
            acc[r][3] = fmaf(w, a.w, acc[r][3]);
            acc[r][4] = fmaf(w, d.x, acc[r][4]);
            acc[r][5] = fmaf(w, d.y, acc[r][5]);
            acc[r][6] = fmaf(w, d.z, acc[r][6]);
            acc[r][7] = fmaf(w, d.w, acc[r][7]);
        }
        w *= DC;
    }
    if (k <= MTERMS) {                 // loop ran k times -> w == DC^k
        #pragma unroll
        for (int r = 0; r < 2; r++) {
            const int i = i0 + r;
            if (i >= j0 && i < j0 + 8) acc[r][i - j0] += w;
        }
    }

    __syncthreads();

    // ---- Emit 16 states, barrier-free, 256-bit streaming stores ----
    float* op = out + ((size_t)b * SEQ + (size_t)k * T_CHUNK) * DIM * DIM;

    #pragma unroll
    for (int t = 0; t < T_CHUNK; t++) {
        const float* row = sc + t * DIM;
        const float  ci0 = row[i0];
        const float  ci1 = row[i0 + 1];
        const float4 cjA = *reinterpret_cast<const float4*>(row + j0);
        const float4 cjB = *reinterpret_cast<const float4*>(row + j0 + 4);
        const float cj[8] = {cjA.x, cjA.y, cjA.z, cjA.w,
                             cjB.x, cjB.y, cjB.z, cjB.w};
        #pragma unroll
        for (int c = 0; c < 8; c++) {
            acc[0][c] = fmaf(acc[0][c], DECAY, ci0 * cj[c]);
            acc[1][c] = fmaf(acc[1][c], DECAY, ci1 * cj[c]);
        }
        float* ot = op + (size_t)t * DIM * DIM;
        stg256_cs(ot + (i0 + 0) * DIM + j0, acc[0]);
        stg256_cs(ot + (i0 + 1) * DIM + j0, acc[1]);
    }
}

// ---------------------------------------------------------------------------
// Launch: B1 (1024 blocks), then states with Programmatic Dependent Launch.
// ---------------------------------------------------------------------------
extern "C" void kernel_launch(void* const* d_in, const int* in_sizes, int n_in,
                              void* d_out, int out_size) {
    const int*   x   = (const int*)d_in[0];     // [B, S] int32
    const float* emb = (const float*)d_in[1];   // [VOCAB, D] fp32
    float*       out = (float*)d_out;           // [B, S, D, D] fp32

    (void)in_sizes; (void)n_in; (void)out_size;

    qmn_chunk_sum<<<BATCH * NCHUNK, 256>>>(x, emb);

    cudaLaunchConfig_t cfg = {};
    cfg.gridDim  = dim3(BATCH * NCHUNK, 1, 1);
    cfg.blockDim = dim3(256, 1, 1);
    cfg.dynamicSmemBytes = 0;
    cudaLaunchAttribute attr[1];
    attr[0].id = cudaLaunchAttributeProgrammaticStreamSerialization;
    attr[0].val.programmaticStreamSerializationAllowed = 1;
    cfg.attrs = attr;
    cfg.numAttrs = 1;
    cudaLaunchKernelEx(&cfg, qmn_states, x, emb, out);
}

// round 16
// speedup vs baseline: 1.3969x; 1.2186x over previous
#include <cuda_runtime.h>

// Problem constants
#define BATCH 32
#define SEQ   512
#define DIM   64
#define VOCAB 32000
#define DECAY 0.9f

#define T_CHUNK 16
#define NCHUNK  32                      // SEQ / T_CHUNK
#define DC      0.1853020188851841f     // 0.9^16 (chunk decay)
#define MTERMS  6                       // carry terms kept; err ~0.9^96 = 4.1e-5

// Scratch: per-chunk local sums L_k [B][NCHUNK][D][D] = 16 MB (L2-resident)
__device__ float g_L[BATCH * NCHUNK * DIM * DIM];

// W[s] = 0.9^((15-s)/2): pre-scale so L accumulates with pure FFMA.
__device__ __constant__ float c_W[T_CHUNK] = {
    0.45375228053933687f, 0.47829690000000000f, 0.50416920059926320f,
    0.53144100000000000f, 0.56018800066584800f, 0.59049000000000000f,
    0.62243111185094220f, 0.65610000000000000f, 0.69159012427882460f,
    0.72900000000000000f, 0.76843347142091620f, 0.81000000000000000f,
    0.85381496824546250f, 0.90000000000000000f, 0.94868329805051380f,
    1.00000000000000000f
};

// ---------------------------------------------------------------------------
// Kernel B1: gather (pre-scaled) + per-chunk local decayed sums.
//   sc[s] = W[s] * c_s  ->  L_k = sum_s sc[s] sc[s]^T
// R10 scalar form, 1024 blocks (proven best).
// ---------------------------------------------------------------------------
__global__ __launch_bounds__(256)
void qmn_chunk_sum(const int* __restrict__ x, const float* __restrict__ emb) {
    __shared__ __align__(16) float sc[T_CHUNK * DIM];   // 4 KB

    const int b   = blockIdx.x >> 5;   // NCHUNK = 32
    const int k   = blockIdx.x & 31;
    const int tid = threadIdx.x;

    {   // one float4 per thread, scaled by W[s]
        const int s  = tid >> 4;
        const int d4 = tid & 15;
        int tok = x[b * SEQ + k * T_CHUNK + s];
        tok = min(max(tok, 0), VOCAB - 1);
        float4 v = reinterpret_cast<const float4*>(emb + (size_t)tok * DIM)[d4];
        const float w = c_W[s];
        v.x *= w; v.y *= w; v.z *= w; v.w *= w;
        reinterpret_cast<float4*>(sc)[tid] = v;
    }
    __syncthreads();

    const int i0 = (tid >> 4) * 4;
    const int j0 = (tid & 15) * 4;

    float4 L[4];
    #pragma unroll
    for (int r = 0; r < 4; r++) L[r] = make_float4(0.f, 0.f, 0.f, 0.f);

    #pragma unroll
    for (int t = 0; t < T_CHUNK; t++) {
        const float4 ci = *reinterpret_cast<const float4*>(sc + t * DIM + i0);
        const float4 cj = *reinterpret_cast<const float4*>(sc + t * DIM + j0);
        const float c[4] = {ci.x, ci.y, ci.z, ci.w};
        #pragma unroll
        for (int r = 0; r < 4; r++) {
            L[r].x = fmaf(c[r], cj.x, L[r].x);
            L[r].y = fmaf(c[r], cj.y, L[r].y);
            L[r].z = fmaf(c[r], cj.z, L[r].z);
            L[r].w = fmaf(c[r], cj.w, L[r].w);
        }
    }

    float* Lp = g_L + (size_t)blockIdx.x * DIM * DIM;
    #pragma unroll
    for (int r = 0; r < 4; r++)
        __stcg(reinterpret_cast<float4*>(Lp + (i0 + r) * DIM + j0), L[r]);
}

// ---------------------------------------------------------------------------
// Kernel C: state emission (1024 blocks), R10 form (proven best), PDL-launched
// so its gather prologue overlaps B1's tail; cudaGridDependencySynchronize()
// gates the g_L reads on B1 completion.
// ---------------------------------------------------------------------------
__global__ __launch_bounds__(256)
void qmn_states(const int* __restrict__ x, const float* __restrict__ emb,
                float* __restrict__ out) {
    __shared__ __align__(16) float sc[T_CHUNK * DIM];   // 4 KB

    const int b   = blockIdx.x >> 5;
    const int k   = blockIdx.x & 31;
    const int tid = threadIdx.x;

    // ---- Gather this chunk's content — independent of B1, overlaps it ----
    {
        const int s  = tid >> 4;
        const int d4 = tid & 15;
        int tok = x[b * SEQ + k * T_CHUNK + s];
        tok = min(max(tok, 0), VOCAB - 1);
        reinterpret_cast<float4*>(sc)[tid] =
            reinterpret_cast<const float4*>(emb + (size_t)tok * DIM)[d4];
    }

    const int i0 = (tid >> 4) * 4;
    const int j0 = (tid & 15) * 4;

    // ---- Wait for B1's grid (and its g_L writes) before the carry reads ----
    cudaGridDependencySynchronize();

    // ---- Truncated carry: acc = sum_m DC^{k-1-m} L_m (+ DC^k I if k<=MTERMS)
    float4 acc[4];
    #pragma unroll
    for (int r = 0; r < 4; r++) acc[r] = make_float4(0.f, 0.f, 0.f, 0.f);

    const float* Lb = g_L + (size_t)b * NCHUNK * DIM * DIM;
    const int mlo = (k - MTERMS > 0) ? (k - MTERMS) : 0;
    float w = 1.0f;
    for (int m = k - 1; m >= mlo; m--) {
        const float* Lp = Lb + (size_t)m * DIM * DIM;
        #pragma unroll
        for (int r = 0; r < 4; r++) {
            const float4 l = *reinterpret_cast<const float4*>(Lp + (i0 + r) * DIM + j0);
            acc[r].x = fmaf(w, l.x, acc[r].x);
            acc[r].y = fmaf(w, l.y, acc[r].y);
            acc[r].z = fmaf(w, l.z, acc[r].z);
            acc[r].w = fmaf(w, l.w, acc[r].w);
        }
        w *= DC;
    }
    if (k <= MTERMS) {                 // loop ran k times -> w == DC^k
        #pragma unroll
        for (int r = 0; r < 4; r++) {
            const int i = i0 + r;
            if (i == j0 + 0) acc[r].x += w;
            if (i == j0 + 1) acc[r].y += w;
            if (i == j0 + 2) acc[r].z += w;
            if (i == j0 + 3) acc[r].w += w;
        }
    }

    __syncthreads();

    // ---- Emit 16 states, barrier-free, streaming stores ----
    float* op = out + ((size_t)b * SEQ + (size_t)k * T_CHUNK) * DIM * DIM;

    #pragma unroll
    for (int t = 0; t < T_CHUNK; t++) {
        const float4 ci = *reinterpret_cast<const float4*>(sc + t * DIM + i0);
        const float4 cj = *reinterpret_cast<const float4*>(sc + t * DIM + j0);
        const float c[4] = {ci.x, ci.y, ci.z, ci.w};
        #pragma unroll
        for (int r = 0; r < 4; r++) {
            acc[r].x = fmaf(acc[r].x, DECAY, c[r] * cj.x);
            acc[r].y = fmaf(acc[r].y, DECAY, c[r] * cj.y);
            acc[r].z = fmaf(acc[r].z, DECAY, c[r] * cj.z);
            acc[r].w = fmaf(acc[r].w, DECAY, c[r] * cj.w);
        }
        float* ot = op + (size_t)t * DIM * DIM;
        #pragma unroll
        for (int r = 0; r < 4; r++)
            __stcs(reinterpret_cast<float4*>(ot + (i0 + r) * DIM + j0), acc[r]);
    }
}

// ---------------------------------------------------------------------------
// Launch: B1 (1024 blocks), then states with Programmatic Dependent Launch.
// ---------------------------------------------------------------------------
extern "C" void kernel_launch(void* const* d_in, const int* in_sizes, int n_in,
                              void* d_out, int out_size) {
    const int*   x   = (const int*)d_in[0];     // [B, S] int32
    const float* emb = (const float*)d_in[1];   // [VOCAB, D] fp32
    float*       out = (float*)d_out;           // [B, S, D, D] fp32

    (void)in_sizes; (void)n_in; (void)out_size;

    qmn_chunk_sum<<<BATCH * NCHUNK, 256>>>(x, emb);

    cudaLaunchConfig_t cfg = {};
    cfg.gridDim  = dim3(BATCH * NCHUNK, 1, 1);
    cfg.blockDim = dim3(256, 1, 1);
    cfg.dynamicSmemBytes = 0;
    cudaLaunchAttribute attr[1];
    attr[0].id = cudaLaunchAttributeProgrammaticStreamSerialization;
    attr[0].val.programmaticStreamSerializationAllowed = 1;
    cfg.attrs = attr;
    cfg.numAttrs = 1;
    cudaLaunchKernelEx(&cfg, qmn_states, x, emb, out);
}